// round 15
// baseline (speedup 1.0000x reference)
#include <cuda_runtime.h>

// Problem constants (static per reference)
#define NEV   250000
#define CB    9
#define HV    180
#define WV    240
#define BB    8
#define PLANE (HV*WV)              // 43200
#define NVOX  (2*CB*PLANE*BB)      // 6,220,800
#define TABN  1025                 // table entries over s in [-1,1], h = 2/1024
#define OUTSZ 640
#define NIMG  (BB * 2 * CB)        // 144 output images

#define BINCELLS 64.0f             // (1/8) / (2/1024)
#define TSCALE   512.0f            // (tn+1) * (1024/2)

// k_front block-range dispatch (champion composition — R8)
#define NB_SEG 256
#define KCH 5
#define NB_TAB_X 5                 // 5 x 256 threads = 1280 >= 1025
#define NB_TAB (NB_TAB_X * (100 / KCH))   // 100
#define NB_VOX (NVOX / 4 / 256)    // 6075, 1 float4/thread
#define NB_FRONT (NB_SEG + NB_TAB + NB_VOX)

// resize block split: pad blocks first (independent), core blocks after
#define NB_PAD  (NIMG * 160 * (OUTSZ / 8) / 256)   // 7200
#define NB_CORE (NIMG * 480 * (OUTSZ / 8) / 256)   // 21600

__device__ float        g_vox[NVOX];
__device__ float        g_tab[TABN];   // zero at start; re-zeroed by k_resize tail
__device__ unsigned int g_bmax[BB];    // ditto

// ---------------------------------------------------------------------------
// k_front: fused {segmax | table | vox-zero} via disjoint block ranges.
// g_tab/g_bmax are zero on entry (launch invariant via k_resize tail).
// ---------------------------------------------------------------------------
__global__ void __launch_bounds__(256) k_front(
    const float* __restrict__ ev,
    const float* __restrict__ W1, const float* __restrict__ b1,
    const float* __restrict__ W2, const float* __restrict__ b2,
    const float* __restrict__ W3, const float* __restrict__ b3)
{
    int bid = blockIdx.x;

    if (bid < NB_SEG) {
        // ---- segmax: per-batch max of t (positive floats: uint order) ----
        __shared__ unsigned int sm[BB];
        if (threadIdx.x < BB) sm[threadIdx.x] = 0u;
        __syncthreads();
        for (int e = bid * 256 + threadIdx.x; e < NEV; e += NB_SEG * 256) {
            float t = __ldg(&ev[5 * e + 2]);
            int   b = (int)__ldg(&ev[5 * e + 4]);
            atomicMax(&sm[b], __float_as_uint(t));
        }
        __syncthreads();
        if (threadIdx.x < BB) atomicMax(&g_bmax[threadIdx.x], sm[threadIdx.x]);
        cudaTriggerProgrammaticLaunchCompletion();
        return;
    }

    if (bid < NB_SEG + NB_TAB) {
        // ---- table: f(s) on 1025-pt grid, KCH=5 neuron chunks ----
        int tb = bid - NB_SEG;
        int bx = tb % NB_TAB_X;
        int k0 = (tb / NB_TAB_X) * KCH;
        __shared__ float sW2[100 * KCH];
        __shared__ float sW1[100], sb1[100];
        for (int i = threadIdx.x; i < 100 * KCH; i += 256)
            sW2[i] = W2[(i / KCH) * 100 + k0 + (i % KCH)];
        if (threadIdx.x < 100) {
            sW1[threadIdx.x] = W1[threadIdx.x];
            sb1[threadIdx.x] = b1[threadIdx.x];
        }
        __syncthreads();
        int e = bx * 256 + threadIdx.x;
        if (e < TABN) {
            float s = (float)e * (2.0f / 1024.0f) - 1.0f;
            float acc[KCH];
#pragma unroll
            for (int k = 0; k < KCH; k++) acc[k] = 0.f;
#pragma unroll 5
            for (int j = 0; j < 100; j++) {
                float pre = fmaf(sW1[j], s, sb1[j]);
                float hj  = fmaxf(pre, 0.1f * pre);   // LeakyReLU(0.1)
#pragma unroll
                for (int k = 0; k < KCH; k++)
                    acc[k] = fmaf(hj, sW2[j * KCH + k], acc[k]);
            }
            float f = (k0 == 0) ? __ldg(&b3[0]) : 0.f;
#pragma unroll
            for (int k = 0; k < KCH; k++) {
                float pre = acc[k] + __ldg(&b2[k0 + k]);
                float h2  = fmaxf(pre, 0.1f * pre);
                f = fmaf(h2, __ldg(&W3[k0 + k]), f);
            }
            atomicAdd(&g_tab[e], f);
        }
        cudaTriggerProgrammaticLaunchCompletion();
        return;
    }

    // ---- vox zero: 1 float4 store per thread ----
    int i = (bid - NB_SEG - NB_TAB) * 256 + threadIdx.x;
    ((float4*)g_vox)[i] = make_float4(0.f, 0.f, 0.f, 0.f);
    cudaTriggerProgrammaticLaunchCompletion();
}

// ---------------------------------------------------------------------------
// scatter (PDL secondary of front): gridsync then 1 event/thread, 9 planar
// fire-and-forget REDs. (Presync-load variant measured no better — REDs have
// no return dependency, so the loads were never on the critical path.)
// ---------------------------------------------------------------------------
__global__ void __launch_bounds__(256) k_scatter(const float* __restrict__ ev) {
    cudaTriggerProgrammaticLaunchCompletion();
    int e = blockIdx.x * blockDim.x + threadIdx.x;
    if (e >= NEV) return;

    cudaGridDependencySynchronize();   // bmax/tab/vox-zero ready

    float x  = __ldg(&ev[5 * e + 0]);
    float y  = __ldg(&ev[5 * e + 1]);
    float t  = __ldg(&ev[5 * e + 2]);
    float p  = __ldg(&ev[5 * e + 3]);
    float bf = __ldg(&ev[5 * e + 4]);
    int b = (int)bf;
    float tn = t / __uint_as_float(g_bmax[b]);      // matches jnp fp32 divide
    int vbase = (int)x + WV * (int)y + (CB * PLANE) * (int)p + (2 * CB * PLANE) * b;
    float u0 = (tn + 1.0f) * TSCALE;                // grid coord of s = tn - 0
#pragma unroll
    for (int i = 0; i < CB; i++) {
        float u = u0 - BINCELLS * (float)i;         // exact fp32 arithmetic
        int i0 = (int)u;
        if (i0 > TABN - 2) i0 = TABN - 2;           // tn == 1.0 edge
        float fr = u - (float)i0;
        float t0 = g_tab[i0], t1 = g_tab[i0 + 1];
        float val = tn * fmaf(fr, t1 - t0, t0);
        atomicAdd(&g_vox[vbase + i * PLANE], val);
    }
}

// ---------------------------------------------------------------------------
// resize (PDL secondary of scatter): pad blocks sync-free (overlap scatter);
// core blocks gridsync then bilinear-resize (8/3 exact scale, compile-time
// weights, streaming stores). Re-zeroes g_tab/g_bmax behind the sync.
// ---------------------------------------------------------------------------
__global__ void __launch_bounds__(256) k_resize(float* __restrict__ out) {
    int bid = blockIdx.x;

    if (bid < NB_PAD) {
        // ---- pad: rows [0,80) and [560,640) = 114.0 (independent) ----
        int gid = bid * 256 + threadIdx.x;
        int m  = gid % (OUTSZ / 8);
        int r  = gid / (OUTSZ / 8);
        int pr = r % 160;
        int bc = r / 160;
        int oy = (pr < 80) ? pr : pr + 480;
        float4* o = (float4*)(out + (((size_t)bc * OUTSZ + oy) * OUTSZ + m * 8));
        float4 v = make_float4(114.f, 114.f, 114.f, 114.f);
        __stcs(o, v);
        __stcs(o + 1, v);
        return;
    }

    cudaGridDependencySynchronize();   // scatter's vox complete

    if (bid == NB_PAD) {               // scatter done; reset launch invariants
        for (int i = threadIdx.x; i < TABN; i += 256) g_tab[i] = 0.f;
        if (threadIdx.x < BB) g_bmax[threadIdx.x] = 0u;
    }

    int gid = (bid - NB_PAD) * 256 + threadIdx.x;   // over 144*480*80
    int m   = gid % (OUTSZ / 8);
    int r   = gid / (OUTSZ / 8);
    int oyr = r % 480;
    int bc  = r / 480;
    int oy  = oyr + 80;
    float4* o = (float4*)(out + (((size_t)bc * OUTSZ + oy) * OUTSZ + m * 8));

    int c = bc % (2 * CB), b = bc / (2 * CB);
    int pp = c / CB, bin = c % CB;
    const float* vb = g_vox + (size_t)PLANE * (bin + CB * (pp + 2 * b));

    float fy  = 0.375f * (float)oyr - 0.3125f;
    float fyf = floorf(fy);
    int   y0  = (int)fyf;
    float wy  = fy - fyf;
    int y0c = y0 < 0 ? 0 : y0;
    int y1c = (y0 + 1 > HV - 1) ? (HV - 1) : (y0 + 1);
    const float* r0 = vb + y0c * WV;
    const float* r1 = vb + y1c * WV;

    int xb = 3 * m - 1;
    float a0[5], a1[5];
#pragma unroll
    for (int i = 0; i < 5; i++) {
        int xc = xb + i;
        xc = xc < 0 ? 0 : (xc > WV - 1 ? WV - 1 : xc);
        a0[i] = __ldg(&r0[xc]);
        a1[i] = __ldg(&r1[xc]);
    }
    const float wx[8] = {0.6875f, 0.0625f, 0.4375f, 0.8125f,
                         0.1875f, 0.5625f, 0.9375f, 0.3125f};
    const int   ix[8] = {0, 1, 1, 1, 2, 2, 2, 3};
    float o8[8];
#pragma unroll
    for (int k = 0; k < 8; k++) {
        int i = ix[k];
        float h0 = fmaf(wx[k], a0[i + 1] - a0[i], a0[i]);
        float h1 = fmaf(wx[k], a1[i + 1] - a1[i], a1[i]);
        o8[k] = fmaf(wy, h1 - h0, h0);
    }
    __stcs(o,     make_float4(o8[0], o8[1], o8[2], o8[3]));
    __stcs(o + 1, make_float4(o8[4], o8[5], o8[6], o8[7]));
}

// ---------------------------------------------------------------------------
// launch: single stream — front -> scatter(PDL) -> resize(PDL).
// Rejected-for-cause across R4-R14: multi-stream fork, 4-ev/thread scatter,
// bin-interleave + v4 RED + transpose, memset node, smem-staged segmax,
// smem-staged resize, presync scatter loads.
// ---------------------------------------------------------------------------
static void launch_pdl(const void* kern, dim3 grid, void** args) {
    cudaLaunchConfig_t cfg = {};
    cfg.gridDim  = grid;
    cfg.blockDim = dim3(256, 1, 1);
    cfg.dynamicSmemBytes = 0;
    cfg.stream = 0;
    cudaLaunchAttribute attr[1];
    attr[0].id = cudaLaunchAttributeProgrammaticStreamSerialization;
    attr[0].val.programmaticStreamSerializationAllowed = 1;
    cfg.attrs = attr;
    cfg.numAttrs = 1;
    cudaLaunchKernelExC(&cfg, kern, args);
}

extern "C" void kernel_launch(void* const* d_in, const int* in_sizes, int n_in,
                              void* d_out, int out_size) {
    const float* ev = (const float*)d_in[0];
    const float* W1 = (const float*)d_in[1];
    const float* b1 = (const float*)d_in[2];
    const float* W2 = (const float*)d_in[3];
    const float* b2 = (const float*)d_in[4];
    const float* W3 = (const float*)d_in[5];
    const float* b3 = (const float*)d_in[6];
    float* out = (float*)d_out;

    k_front<<<NB_FRONT, 256>>>(ev, W1, b1, W2, b2, W3, b3);

    {   // scatter: PDL secondary of front
        void* args[] = {(void*)&ev};
        launch_pdl((const void*)k_scatter, dim3((NEV + 255) / 256, 1, 1), args);
    }
    {   // resize: PDL secondary of scatter (pad blocks overlap scatter)
        void* args[] = {(void*)&out};
        launch_pdl((const void*)k_resize, dim3(NB_PAD + NB_CORE, 1, 1), args);
    }
}

// round 16
// speedup vs baseline: 1.6242x; 1.6242x over previous
#include <cuda_runtime.h>

// Problem constants (static per reference)
#define NEV   250000
#define CB    9
#define HV    180
#define WV    240
#define BB    8
#define PLANE (HV*WV)              // 43200
#define NVOX  (2*CB*PLANE*BB)      // 6,220,800
#define TABN  1025                 // table entries over s in [-1,1], h = 2/1024
#define OUTSZ 640
#define NIMG  (BB * 2 * CB)        // 144 output images

#define BINCELLS 64.0f             // (1/8) / (2/1024)
#define TSCALE   512.0f            // (tn+1) * (1024/2)

// k_front block-range dispatch (segmax/table first so they overlap vox-zero)
#define NB_SEG 256
#define KCH 5
#define NB_TAB_X 5                 // 5 x 256 threads = 1280 >= 1025
#define NB_TAB (NB_TAB_X * (100 / KCH))   // 100
#define NB_VOX (NVOX / 4 / 256)    // 6075 (exact), 1 float4 per thread
#define NB_FRONT (NB_SEG + NB_TAB + NB_VOX)

// resize block split: pad blocks first (independent), core blocks after
#define NB_PAD  (NIMG * 160 * (OUTSZ / 8) / 256)   // 7200
#define NB_CORE (NIMG * 480 * (OUTSZ / 8) / 256)   // 21600

__device__ float        g_vox[NVOX];
__device__ float        g_tab[TABN];   // zero at start; re-zeroed by k_resize tail
__device__ unsigned int g_bmax[BB];    // ditto

// ---------------------------------------------------------------------------
// k_front: fused {segmax | table | vox-zero} via disjoint block ranges.
// Plain stream node — NO PDL triggers (R8 form; the champion).
// ---------------------------------------------------------------------------
__global__ void __launch_bounds__(256) k_front(
    const float* __restrict__ ev,
    const float* __restrict__ W1, const float* __restrict__ b1,
    const float* __restrict__ W2, const float* __restrict__ b2,
    const float* __restrict__ W3, const float* __restrict__ b3)
{
    int bid = blockIdx.x;

    if (bid < NB_SEG) {
        // ---- segmax: per-batch max of t (positive floats: uint order) ----
        __shared__ unsigned int sm[BB];
        if (threadIdx.x < BB) sm[threadIdx.x] = 0u;
        __syncthreads();
        for (int e = bid * 256 + threadIdx.x; e < NEV; e += NB_SEG * 256) {
            float t = __ldg(&ev[5 * e + 2]);
            int   b = (int)__ldg(&ev[5 * e + 4]);
            atomicMax(&sm[b], __float_as_uint(t));
        }
        __syncthreads();
        if (threadIdx.x < BB) atomicMax(&g_bmax[threadIdx.x], sm[threadIdx.x]);
        return;
    }

    if (bid < NB_SEG + NB_TAB) {
        // ---- table: f(s) on 1025-pt grid, KCH=5 neuron chunks ----
        int tb = bid - NB_SEG;
        int bx = tb % NB_TAB_X;
        int k0 = (tb / NB_TAB_X) * KCH;
        __shared__ float sW2[100 * KCH];
        __shared__ float sW1[100], sb1[100];
        for (int i = threadIdx.x; i < 100 * KCH; i += 256)
            sW2[i] = W2[(i / KCH) * 100 + k0 + (i % KCH)];
        if (threadIdx.x < 100) {
            sW1[threadIdx.x] = W1[threadIdx.x];
            sb1[threadIdx.x] = b1[threadIdx.x];
        }
        __syncthreads();
        int e = bx * 256 + threadIdx.x;
        if (e >= TABN) return;
        float s = (float)e * (2.0f / 1024.0f) - 1.0f;
        float acc[KCH];
#pragma unroll
        for (int k = 0; k < KCH; k++) acc[k] = 0.f;
#pragma unroll 5
        for (int j = 0; j < 100; j++) {
            float pre = fmaf(sW1[j], s, sb1[j]);
            float hj  = fmaxf(pre, 0.1f * pre);   // LeakyReLU(0.1)
#pragma unroll
            for (int k = 0; k < KCH; k++)
                acc[k] = fmaf(hj, sW2[j * KCH + k], acc[k]);
        }
        float f = (k0 == 0) ? __ldg(&b3[0]) : 0.f;
#pragma unroll
        for (int k = 0; k < KCH; k++) {
            float pre = acc[k] + __ldg(&b2[k0 + k]);
            float h2  = fmaxf(pre, 0.1f * pre);
            f = fmaf(h2, __ldg(&W3[k0 + k]), f);
        }
        atomicAdd(&g_tab[e], f);
        return;
    }

    // ---- vox zero: 1 float4 store per thread ----
    int i = (bid - NB_SEG - NB_TAB) * 256 + threadIdx.x;
    ((float4*)g_vox)[i] = make_float4(0.f, 0.f, 0.f, 0.f);
}

// ---------------------------------------------------------------------------
// scatter: PLAIN stream node after front (stream order gates it — launching
// it as a PDL secondary with an in-kernel gridsync regressed badly in R15:
// all 977 blocks release simultaneously into a synchronized RED burst).
// It only TRIGGERS PDL at entry so resize's pad blocks can overlap it.
// ---------------------------------------------------------------------------
__global__ void __launch_bounds__(256) k_scatter(const float* __restrict__ ev) {
    cudaTriggerProgrammaticLaunchCompletion();
    int e = blockIdx.x * blockDim.x + threadIdx.x;
    if (e >= NEV) return;
    float x  = __ldg(&ev[5 * e + 0]);
    float y  = __ldg(&ev[5 * e + 1]);
    float t  = __ldg(&ev[5 * e + 2]);
    float p  = __ldg(&ev[5 * e + 3]);
    float bf = __ldg(&ev[5 * e + 4]);
    int b = (int)bf;
    float tn = t / __uint_as_float(g_bmax[b]);      // matches jnp fp32 divide
    int vbase = (int)x + WV * (int)y + (CB * PLANE) * (int)p + (2 * CB * PLANE) * b;
    float u0 = (tn + 1.0f) * TSCALE;                // grid coord of s = tn - 0
#pragma unroll
    for (int i = 0; i < CB; i++) {
        float u = u0 - BINCELLS * (float)i;         // exact fp32 arithmetic
        int i0 = (int)u;
        if (i0 > TABN - 2) i0 = TABN - 2;           // tn == 1.0 edge
        float fr = u - (float)i0;
        float t0 = g_tab[i0], t1 = g_tab[i0 + 1];
        float val = tn * fmaf(fr, t1 - t0, t0);
        atomicAdd(&g_vox[vbase + i * PLANE], val);
    }
}

// ---------------------------------------------------------------------------
// resize (the ONLY PDL secondary): pad blocks [0, NB_PAD) write the 114-rows
// with no dependency on scatter -> run concurrently with it. Core blocks
// gridsync before reading vox. g_tab/g_bmax re-zero behind the sync.
// ---------------------------------------------------------------------------
__global__ void __launch_bounds__(256) k_resize(float* __restrict__ out) {
    int bid = blockIdx.x;

    if (bid < NB_PAD) {
        // ---- pad: rows [0,80) and [560,640) = 114.0 (independent) ----
        int gid = bid * 256 + threadIdx.x;
        int m  = gid % (OUTSZ / 8);
        int r  = gid / (OUTSZ / 8);
        int pr = r % 160;
        int bc = r / 160;
        int oy = (pr < 80) ? pr : pr + 480;
        float4* o = (float4*)(out + (((size_t)bc * OUTSZ + oy) * OUTSZ + m * 8));
        float4 v = make_float4(114.f, 114.f, 114.f, 114.f);
        __stcs(o, v);
        __stcs(o + 1, v);
        return;
    }

    cudaGridDependencySynchronize();   // scatter's vox complete

    if (bid == NB_PAD) {               // scatter done; reset launch invariants
        for (int i = threadIdx.x; i < TABN; i += 256) g_tab[i] = 0.f;
        if (threadIdx.x < BB) g_bmax[threadIdx.x] = 0u;
    }

    int gid = (bid - NB_PAD) * 256 + threadIdx.x;   // over 144*480*80
    int m   = gid % (OUTSZ / 8);
    int r   = gid / (OUTSZ / 8);
    int oyr = r % 480;
    int bc  = r / 480;
    int oy  = oyr + 80;
    float4* o = (float4*)(out + (((size_t)bc * OUTSZ + oy) * OUTSZ + m * 8));

    int c = bc % (2 * CB), b = bc / (2 * CB);
    int pp = c / CB, bin = c % CB;
    const float* vb = g_vox + (size_t)PLANE * (bin + CB * (pp + 2 * b));

    float fy  = 0.375f * (float)oyr - 0.3125f;
    float fyf = floorf(fy);
    int   y0  = (int)fyf;
    float wy  = fy - fyf;
    int y0c = y0 < 0 ? 0 : y0;
    int y1c = (y0 + 1 > HV - 1) ? (HV - 1) : (y0 + 1);
    const float* r0 = vb + y0c * WV;
    const float* r1 = vb + y1c * WV;

    int xb = 3 * m - 1;
    float a0[5], a1[5];
#pragma unroll
    for (int i = 0; i < 5; i++) {
        int xc = xb + i;
        xc = xc < 0 ? 0 : (xc > WV - 1 ? WV - 1 : xc);
        a0[i] = __ldg(&r0[xc]);
        a1[i] = __ldg(&r1[xc]);
    }
    const float wx[8] = {0.6875f, 0.0625f, 0.4375f, 0.8125f,
                         0.1875f, 0.5625f, 0.9375f, 0.3125f};
    const int   ix[8] = {0, 1, 1, 1, 2, 2, 2, 3};
    float o8[8];
#pragma unroll
    for (int k = 0; k < 8; k++) {
        int i = ix[k];
        float h0 = fmaf(wx[k], a0[i + 1] - a0[i], a0[i]);
        float h1 = fmaf(wx[k], a1[i + 1] - a1[i], a1[i]);
        o8[k] = fmaf(wy, h1 - h0, h0);
    }
    __stcs(o,     make_float4(o8[0], o8[1], o8[2], o8[3]));
    __stcs(o + 1, make_float4(o8[4], o8[5], o8[6], o8[7]));
}

// ---------------------------------------------------------------------------
// launch: single stream — front (plain) -> scatter (plain, triggers PDL) ->
// resize (PDL secondary; pad blocks overlap scatter). Exact R8 winner.
// Rejected-for-cause R4-R15: multi-stream fork, 4-ev/thread scatter,
// interleave+v4RED+transpose, memset node, smem segmax, smem resize,
// scatter-as-PDL-secondary (with or without presync loads).
// ---------------------------------------------------------------------------
extern "C" void kernel_launch(void* const* d_in, const int* in_sizes, int n_in,
                              void* d_out, int out_size) {
    const float* ev = (const float*)d_in[0];
    const float* W1 = (const float*)d_in[1];
    const float* b1 = (const float*)d_in[2];
    const float* W2 = (const float*)d_in[3];
    const float* b2 = (const float*)d_in[4];
    const float* W3 = (const float*)d_in[5];
    const float* b3 = (const float*)d_in[6];
    float* out = (float*)d_out;

    k_front<<<NB_FRONT, 256>>>(ev, W1, b1, W2, b2, W3, b3);
    k_scatter<<<(NEV + 255) / 256, 256>>>(ev);

    cudaLaunchConfig_t cfg = {};
    cfg.gridDim  = dim3(NB_PAD + NB_CORE, 1, 1);
    cfg.blockDim = dim3(256, 1, 1);
    cfg.dynamicSmemBytes = 0;
    cfg.stream = 0;
    cudaLaunchAttribute attr[1];
    attr[0].id = cudaLaunchAttributeProgrammaticStreamSerialization;
    attr[0].val.programmaticStreamSerializationAllowed = 1;
    cfg.attrs = attr;
    cfg.numAttrs = 1;
    cudaLaunchKernelEx(&cfg, k_resize, out);
}

// round 17
// speedup vs baseline: 1.6311x; 1.0042x over previous
#include <cuda_runtime.h>

// Problem constants (static per reference)
#define NEV   250000
#define CB    9
#define HV    180
#define WV    240
#define BB    8
#define PLANE (HV*WV)              // 43200
#define NVOX  (2*CB*PLANE*BB)      // 6,220,800
#define TABN  1025                 // table entries over s in [-1,1], h = 2/1024
#define OUTSZ 640
#define NIMG  (BB * 2 * CB)        // 144 output images

#define BINCELLS 64.0f             // (1/8) / (2/1024)
#define TSCALE   512.0f            // (tn+1) * (1024/2)

// k_front block-range dispatch (segmax/table first so they overlap vox-zero)
// NB_SEG raised 256 -> 977 (1 event/thread): segmax was DRAM-latency bound at
// ~1.7 early blocks/SM with a 4-deep loop; this gives scatter-like parallelism.
#define NB_SEG ((NEV + 255) / 256)        // 977
#define KCH 5
#define NB_TAB_X 5                        // 5 x 256 threads = 1280 >= 1025
#define NB_TAB (NB_TAB_X * (100 / KCH))   // 100
#define NB_VOX (NVOX / 4 / 256)           // 6075 (exact), 1 float4 per thread
#define NB_FRONT (NB_SEG + NB_TAB + NB_VOX)

// resize block split: pad blocks first (independent), core blocks after
#define NB_PAD  (NIMG * 160 * (OUTSZ / 8) / 256)   // 7200
#define NB_CORE (NIMG * 480 * (OUTSZ / 8) / 256)   // 21600

__device__ float        g_vox[NVOX];
__device__ float        g_tab[TABN];   // zero at start; re-zeroed by k_resize tail
__device__ unsigned int g_bmax[BB];    // ditto

// ---------------------------------------------------------------------------
// k_front: fused {segmax | table | vox-zero} via disjoint block ranges.
// Plain stream node — NO PDL machinery (twice-confirmed champion structure).
// ---------------------------------------------------------------------------
__global__ void __launch_bounds__(256) k_front(
    const float* __restrict__ ev,
    const float* __restrict__ W1, const float* __restrict__ b1,
    const float* __restrict__ W2, const float* __restrict__ b2,
    const float* __restrict__ W3, const float* __restrict__ b3)
{
    int bid = blockIdx.x;

    if (bid < NB_SEG) {
        // ---- segmax: 1 event/thread (positive floats: uint order) ----
        __shared__ unsigned int sm[BB];
        if (threadIdx.x < BB) sm[threadIdx.x] = 0u;
        __syncthreads();
        int e = bid * 256 + threadIdx.x;
        if (e < NEV) {
            float t = __ldg(&ev[5 * e + 2]);
            int   b = (int)__ldg(&ev[5 * e + 4]);
            atomicMax(&sm[b], __float_as_uint(t));
        }
        __syncthreads();
        if (threadIdx.x < BB) atomicMax(&g_bmax[threadIdx.x], sm[threadIdx.x]);
        return;
    }

    if (bid < NB_SEG + NB_TAB) {
        // ---- table: f(s) on 1025-pt grid, KCH=5 neuron chunks ----
        int tb = bid - NB_SEG;
        int bx = tb % NB_TAB_X;
        int k0 = (tb / NB_TAB_X) * KCH;
        __shared__ float sW2[100 * KCH];
        __shared__ float sW1[100], sb1[100];
        for (int i = threadIdx.x; i < 100 * KCH; i += 256)
            sW2[i] = W2[(i / KCH) * 100 + k0 + (i % KCH)];
        if (threadIdx.x < 100) {
            sW1[threadIdx.x] = W1[threadIdx.x];
            sb1[threadIdx.x] = b1[threadIdx.x];
        }
        __syncthreads();
        int e = bx * 256 + threadIdx.x;
        if (e >= TABN) return;
        float s = (float)e * (2.0f / 1024.0f) - 1.0f;
        float acc[KCH];
#pragma unroll
        for (int k = 0; k < KCH; k++) acc[k] = 0.f;
#pragma unroll 5
        for (int j = 0; j < 100; j++) {
            float pre = fmaf(sW1[j], s, sb1[j]);
            float hj  = fmaxf(pre, 0.1f * pre);   // LeakyReLU(0.1)
#pragma unroll
            for (int k = 0; k < KCH; k++)
                acc[k] = fmaf(hj, sW2[j * KCH + k], acc[k]);
        }
        float f = (k0 == 0) ? __ldg(&b3[0]) : 0.f;
#pragma unroll
        for (int k = 0; k < KCH; k++) {
            float pre = acc[k] + __ldg(&b2[k0 + k]);
            float h2  = fmaxf(pre, 0.1f * pre);
            f = fmaf(h2, __ldg(&W3[k0 + k]), f);
        }
        atomicAdd(&g_tab[e], f);
        return;
    }

    // ---- vox zero: 1 float4 store per thread ----
    int i = (bid - NB_SEG - NB_TAB) * 256 + threadIdx.x;
    ((float4*)g_vox)[i] = make_float4(0.f, 0.f, 0.f, 0.f);
}

// ---------------------------------------------------------------------------
// scatter: PLAIN stream node after front (scatter-as-PDL-secondary regressed
// in R15 — synchronized RED burst). It only TRIGGERS PDL at entry so
// resize's pad blocks can overlap it.
// ---------------------------------------------------------------------------
__global__ void __launch_bounds__(256) k_scatter(const float* __restrict__ ev) {
    cudaTriggerProgrammaticLaunchCompletion();
    int e = blockIdx.x * blockDim.x + threadIdx.x;
    if (e >= NEV) return;
    float x  = __ldg(&ev[5 * e + 0]);
    float y  = __ldg(&ev[5 * e + 1]);
    float t  = __ldg(&ev[5 * e + 2]);
    float p  = __ldg(&ev[5 * e + 3]);
    float bf = __ldg(&ev[5 * e + 4]);
    int b = (int)bf;
    float tn = t / __uint_as_float(g_bmax[b]);      // matches jnp fp32 divide
    int vbase = (int)x + WV * (int)y + (CB * PLANE) * (int)p + (2 * CB * PLANE) * b;
    float u0 = (tn + 1.0f) * TSCALE;                // grid coord of s = tn - 0
#pragma unroll
    for (int i = 0; i < CB; i++) {
        float u = u0 - BINCELLS * (float)i;         // exact fp32 arithmetic
        int i0 = (int)u;
        if (i0 > TABN - 2) i0 = TABN - 2;           // tn == 1.0 edge
        float fr = u - (float)i0;
        float t0 = g_tab[i0], t1 = g_tab[i0 + 1];
        float val = tn * fmaf(fr, t1 - t0, t0);
        atomicAdd(&g_vox[vbase + i * PLANE], val);
    }
}

// ---------------------------------------------------------------------------
// resize (the ONLY PDL secondary): pad blocks [0, NB_PAD) write the 114-rows
// with no dependency on scatter -> run concurrently with it. Core blocks
// gridsync before reading vox. g_tab/g_bmax re-zero behind the sync.
// ---------------------------------------------------------------------------
__global__ void __launch_bounds__(256) k_resize(float* __restrict__ out) {
    int bid = blockIdx.x;

    if (bid < NB_PAD) {
        // ---- pad: rows [0,80) and [560,640) = 114.0 (independent) ----
        int gid = bid * 256 + threadIdx.x;
        int m  = gid % (OUTSZ / 8);
        int r  = gid / (OUTSZ / 8);
        int pr = r % 160;
        int bc = r / 160;
        int oy = (pr < 80) ? pr : pr + 480;
        float4* o = (float4*)(out + (((size_t)bc * OUTSZ + oy) * OUTSZ + m * 8));
        float4 v = make_float4(114.f, 114.f, 114.f, 114.f);
        __stcs(o, v);
        __stcs(o + 1, v);
        return;
    }

    cudaGridDependencySynchronize();   // scatter's vox complete

    if (bid == NB_PAD) {               // scatter done; reset launch invariants
        for (int i = threadIdx.x; i < TABN; i += 256) g_tab[i] = 0.f;
        if (threadIdx.x < BB) g_bmax[threadIdx.x] = 0u;
    }

    int gid = (bid - NB_PAD) * 256 + threadIdx.x;   // over 144*480*80
    int m   = gid % (OUTSZ / 8);
    int r   = gid / (OUTSZ / 8);
    int oyr = r % 480;
    int bc  = r / 480;
    int oy  = oyr + 80;
    float4* o = (float4*)(out + (((size_t)bc * OUTSZ + oy) * OUTSZ + m * 8));

    int c = bc % (2 * CB), b = bc / (2 * CB);
    int pp = c / CB, bin = c % CB;
    const float* vb = g_vox + (size_t)PLANE * (bin + CB * (pp + 2 * b));

    float fy  = 0.375f * (float)oyr - 0.3125f;
    float fyf = floorf(fy);
    int   y0  = (int)fyf;
    float wy  = fy - fyf;
    int y0c = y0 < 0 ? 0 : y0;
    int y1c = (y0 + 1 > HV - 1) ? (HV - 1) : (y0 + 1);
    const float* r0 = vb + y0c * WV;
    const float* r1 = vb + y1c * WV;

    int xb = 3 * m - 1;
    float a0[5], a1[5];
#pragma unroll
    for (int i = 0; i < 5; i++) {
        int xc = xb + i;
        xc = xc < 0 ? 0 : (xc > WV - 1 ? WV - 1 : xc);
        a0[i] = __ldg(&r0[xc]);
        a1[i] = __ldg(&r1[xc]);
    }
    const float wx[8] = {0.6875f, 0.0625f, 0.4375f, 0.8125f,
                         0.1875f, 0.5625f, 0.9375f, 0.3125f};
    const int   ix[8] = {0, 1, 1, 1, 2, 2, 2, 3};
    float o8[8];
#pragma unroll
    for (int k = 0; k < 8; k++) {
        int i = ix[k];
        float h0 = fmaf(wx[k], a0[i + 1] - a0[i], a0[i]);
        float h1 = fmaf(wx[k], a1[i + 1] - a1[i], a1[i]);
        o8[k] = fmaf(wy, h1 - h0, h0);
    }
    __stcs(o,     make_float4(o8[0], o8[1], o8[2], o8[3]));
    __stcs(o + 1, make_float4(o8[4], o8[5], o8[6], o8[7]));
}

// ---------------------------------------------------------------------------
// launch: single stream — front (plain) -> scatter (plain, triggers PDL) ->
// resize (PDL secondary; pad blocks overlap scatter).
// Rejected-for-cause R4-R15: multi-stream fork, 4-ev/thread scatter,
// interleave+v4RED+transpose, memset node, smem segmax, smem resize,
// scatter-as-PDL-secondary.
// ---------------------------------------------------------------------------
extern "C" void kernel_launch(void* const* d_in, const int* in_sizes, int n_in,
                              void* d_out, int out_size) {
    const float* ev = (const float*)d_in[0];
    const float* W1 = (const float*)d_in[1];
    const float* b1 = (const float*)d_in[2];
    const float* W2 = (const float*)d_in[3];
    const float* b2 = (const float*)d_in[4];
    const float* W3 = (const float*)d_in[5];
    const float* b3 = (const float*)d_in[6];
    float* out = (float*)d_out;

    k_front<<<NB_FRONT, 256>>>(ev, W1, b1, W2, b2, W3, b3);
    k_scatter<<<(NEV + 255) / 256, 256>>>(ev);

    cudaLaunchConfig_t cfg = {};
    cfg.gridDim  = dim3(NB_PAD + NB_CORE, 1, 1);
    cfg.blockDim = dim3(256, 1, 1);
    cfg.dynamicSmemBytes = 0;
    cfg.stream = 0;
    cudaLaunchAttribute attr[1];
    attr[0].id = cudaLaunchAttributeProgrammaticStreamSerialization;
    attr[0].val.programmaticStreamSerializationAllowed = 1;
    cfg.attrs = attr;
    cfg.numAttrs = 1;
    cudaLaunchKernelEx(&cfg, k_resize, out);
}